// round 4
// baseline (speedup 1.0000x reference)
#include <cuda_runtime.h>
#include <cuda_bf16.h>
#include <cstdint>
#include <math.h>

#define B_ 128
#define T_ 64
#define E_ 2048
#define H_ 1024
#define R_ 8
#define H3 3072

// ==================== helpers (baseline PTX only) ====================
__device__ __forceinline__ uint32_t smem_to_u32(const void* p) {
    uint32_t a;
    asm("{ .reg .u64 t; cvta.to.shared.u64 t, %1; cvt.u32.u64 %0, t; }"
        : "=r"(a) : "l"(p));
    return a;
}
__device__ __forceinline__ uint32_t swz(uint32_t b) { return b ^ ((b >> 3) & 0x70); }

__device__ __forceinline__ void cpa16(uint32_t dst, const void* src) {
    asm volatile("cp.async.cg.shared.global [%0], [%1], 16;" :: "r"(dst), "l"(src));
}
__device__ __forceinline__ void ldm_x4(uint32_t* r, uint32_t a) {
    asm volatile("ldmatrix.sync.aligned.m8n8.x4.shared.b16 {%0,%1,%2,%3}, [%4];"
                 : "=r"(r[0]), "=r"(r[1]), "=r"(r[2]), "=r"(r[3]) : "r"(a));
}
__device__ __forceinline__ void mma16816(float* c, const uint32_t* a, const uint32_t* b) {
    asm volatile(
        "mma.sync.aligned.m16n8k16.row.col.f32.bf16.bf16.f32 "
        "{%0,%1,%2,%3}, {%4,%5,%6,%7}, {%8,%9}, {%0,%1,%2,%3};"
        : "+f"(c[0]), "+f"(c[1]), "+f"(c[2]), "+f"(c[3])
        : "r"(a[0]), "r"(a[1]), "r"(a[2]), "r"(a[3]), "r"(b[0]), "r"(b[1]));
}

// ==================== scratch (static device, allocation-free) ====================
__device__ float d_GI_s[(size_t)B_ * T_ * H3];
__device__ float d_GI_a[(size_t)B_ * T_ * H3];
__device__ float d_GI_o[(size_t)B_ * T_ * H3];
__device__ float d_G[1280 * H3];

__device__ __nv_bfloat16 d_enc_hi[(size_t)B_ * T_ * E_];
__device__ __nv_bfloat16 d_enc_lo[(size_t)B_ * T_ * E_];
__device__ __nv_bfloat16 d_S_hi[(size_t)B_ * R_ * H_];
__device__ __nv_bfloat16 d_S_lo[(size_t)B_ * R_ * H_];

// Weight images packed in mma.sync B-fragment order, hi+lo interleaved.
// u32 index for (n,k,sel):
//   (nt*(Kw>>6)+cc)*16384 + ((g32*4+ks)*32 + l)*16 + sel*8 + j*2 + reg
// with nt=n>>8, g32=(n>>5)&7, j=(n>>3)&3, cc=k>>6, ks=(k>>4)&3,
// kk=k&15, l=((n&7)<<2)|((kk&7)>>1), reg=kk>>3, half=k&1 (bf16 within u32).
__device__ __align__(16) __nv_bfloat16 d_img_hh_s[3072 * 1024 * 2];
__device__ __align__(16) __nv_bfloat16 d_img_hh_a[3072 * 1024 * 2];
__device__ __align__(16) __nv_bfloat16 d_img_hh_o[3072 * 1024 * 2];
__device__ __align__(16) __nv_bfloat16 d_img_ihE_s[3072 * 2048 * 2];
__device__ __align__(16) __nv_bfloat16 d_img_ihE_a[3072 * 2048 * 2];
__device__ __align__(16) __nv_bfloat16 d_img_ihE_o[3072 * 2048 * 2];
__device__ __align__(16) __nv_bfloat16 d_img_ihH_s[3072 * 1024 * 2];
__device__ __align__(16) __nv_bfloat16 d_img_ihH_a[3072 * 1024 * 2];

// ==================== conversion kernels ====================
__global__ void conv_enc(const float* __restrict__ enc) {
    size_t idx = (size_t)blockIdx.x * 256 + threadIdx.x;
    float x = enc[idx];
    __nv_bfloat16 h = __float2bfloat16(x);
    d_enc_hi[idx] = h;
    d_enc_lo[idx] = __float2bfloat16(x - __bfloat162float(h));
}

__device__ __forceinline__ size_t wimg_off(int n, int k, int sel, int kw_chunks) {
    int nt = n >> 8, g32 = (n >> 5) & 7, j = (n >> 3) & 3;
    int cc = k >> 6, ks = (k >> 4) & 3, kk = k & 15;
    int l = ((n & 7) << 2) | ((kk & 7) >> 1);
    int reg = (kk >> 3) & 1, half = k & 1;
    size_t u32i = ((size_t)(nt * kw_chunks + cc) << 14)
                + (size_t)(((g32 << 2) + ks) * 32 + l) * 16
                + (sel << 3) + (j << 1) + reg;
    return (u32i << 1) + half;
}

// all 8 weight conversions in one kernel; z selects matrix
__global__ void conv_all(const float* __restrict__ ws_hh, const float* __restrict__ wa_hh,
                         const float* __restrict__ wo_hh, const float* __restrict__ ws_ih,
                         const float* __restrict__ wa_ih, const float* __restrict__ wo_ih) {
    int z = blockIdx.z;
    const float* src;
    __nv_bfloat16* img;
    int ld, off, kb;
    switch (z) {
        case 0: src = ws_hh; img = d_img_hh_s;  ld = 1024; off = 0;    kb = 10; break;
        case 1: src = wa_hh; img = d_img_hh_a;  ld = 1024; off = 0;    kb = 10; break;
        case 2: src = wo_hh; img = d_img_hh_o;  ld = 1024; off = 0;    kb = 10; break;
        case 3: src = ws_ih; img = d_img_ihE_s; ld = 3072; off = 0;    kb = 11; break;
        case 4: src = wa_ih; img = d_img_ihE_a; ld = 3072; off = 0;    kb = 11; break;
        case 5: src = wo_ih; img = d_img_ihE_o; ld = 2048; off = 0;    kb = 11; break;
        case 6: src = ws_ih; img = d_img_ihH_s; ld = 3072; off = 2048; kb = 10; break;
        default: src = wa_ih; img = d_img_ihH_a; ld = 3072; off = 2048; kb = 10; break;
    }
    size_t idx = (size_t)blockIdx.x * 256 + threadIdx.x;
    if (idx >= ((size_t)3072 << kb)) return;
    int n = (int)(idx >> kb);
    int k = (int)(idx & ((1 << kb) - 1));
    float x = src[(size_t)n * ld + off + k];
    __nv_bfloat16 h = __float2bfloat16(x);
    __nv_bfloat16 l = __float2bfloat16(x - __bfloat162float(h));
    int kwc = 1 << (kb - 6);
    img[wimg_off(n, k, 0, kwc)] = h;
    img[wimg_off(n, k, 1, kwc)] = l;
}

// ==================== GEMM core (A via smem/ldmatrix, W direct-to-register) ====================
static constexpr int PF = 3;                     // prefetch depth (4 stages)
static constexpr int STAGE_BYTES = 32768;        // A hi 16K + A lo 16K
static constexpr int SMEM_TOTAL = 1024 + 4 * STAGE_BYTES;  // 132 KB

__device__ __forceinline__ void load_a_chunk(uint32_t st, const __nv_bfloat16* __restrict__ Ahi,
                                             const __nv_bfloat16* __restrict__ Alo, int astride,
                                             const int* __restrict__ rowmap, int koff, int tid) {
#pragma unroll
    for (int i = 0; i < 2; i++) {
        int lin = tid + (i << 9);
        int row = lin >> 3, seg = lin & 7;
        uint32_t so = swz((uint32_t)((row << 7) + (seg << 4)));
        size_t goff = (size_t)rowmap[row] * astride + koff + (seg << 3);
        cpa16(st + so, Ahi + goff);
        cpa16(st + 16384 + so, Alo + goff);
    }
    asm volatile("cp.async.commit_group;" ::: "memory");
}

// C(128x256) = Arows(128 x K) * W(256 x K)^T, hi/lo 3-pass bf16
__device__ void tc_gemm(const __nv_bfloat16* __restrict__ Ahi,
                        const __nv_bfloat16* __restrict__ Alo, int astride, int kchunks,
                        const __nv_bfloat16* __restrict__ Wimg,   // pre-offset to this ntile
                        const int* __restrict__ rowmap, float* __restrict__ Cmn) {
    extern __shared__ char smem[];
    uint32_t sb = smem_to_u32(smem) + 1024;
    const int tid = threadIdx.x;
    const int wid = tid >> 5;
    const int lid = tid & 31;
    const int wm = (wid >> 3) << 6;   // 0 or 64
    const int g32 = wid & 7;          // n-group of 32 cols

    const int a_r = (lid & 7) | (((lid >> 3) & 1) << 3);
    const int a_kb = ((lid >> 4) & 1) << 4;

    float acc[4][4][4];
#pragma unroll
    for (int i = 0; i < 4; i++)
#pragma unroll
        for (int j = 0; j < 4; j++)
#pragma unroll
            for (int q = 0; q < 4; q++) acc[i][j][q] = 0.f;

#pragma unroll
    for (int c = 0; c < PF; c++)
        if (c < kchunks) load_a_chunk(sb + (c & 3) * STAGE_BYTES, Ahi, Alo, astride, rowmap, c << 6, tid);

    for (int c = 0; c < kchunks; c++) {
        int tgt = kchunks - 1 - c;
        if (tgt > PF - 1) tgt = PF - 1;
        if (tgt >= 2)      asm volatile("cp.async.wait_group 2;" ::: "memory");
        else if (tgt == 1) asm volatile("cp.async.wait_group 1;" ::: "memory");
        else               asm volatile("cp.async.wait_group 0;" ::: "memory");
        __syncthreads();
        if (c + PF < kchunks)
            load_a_chunk(sb + ((c + PF) & 3) * STAGE_BYTES, Ahi, Alo, astride, rowmap,
                         (c + PF) << 6, tid);

        uint32_t stA = sb + (c & 3) * STAGE_BYTES;
        const uint4* wq = (const uint4*)(Wimg + ((size_t)c << 15));
#pragma unroll
        for (int ks = 0; ks < 4; ks++) {
            int wi = ((((g32 << 2) + ks) << 5) + lid) << 2;
            uint4 h0 = wq[wi], h1 = wq[wi + 1], l0 = wq[wi + 2], l1 = wq[wi + 3];
            uint32_t wh[8] = {h0.x, h0.y, h0.z, h0.w, h1.x, h1.y, h1.z, h1.w};
            uint32_t wl[8] = {l0.x, l0.y, l0.z, l0.w, l1.x, l1.y, l1.z, l1.w};
#pragma unroll
            for (int mt = 0; mt < 4; mt++) {
                uint32_t ah[4], al[4];
                uint32_t aoff = swz((uint32_t)(((wm + (mt << 4) + a_r) << 7) + (ks << 5) + a_kb));
                ldm_x4(ah, stA + aoff);
                ldm_x4(al, stA + 16384 + aoff);
#pragma unroll
                for (int nt = 0; nt < 4; nt++) {
                    mma16816(acc[mt][nt], ah, wh + (nt << 1));
                    mma16816(acc[mt][nt], al, wh + (nt << 1));
                    mma16816(acc[mt][nt], ah, wl + (nt << 1));
                }
            }
        }
        __syncthreads();
    }

    // epilogue
    const int wn = g32 << 5;
    const int mrow = lid >> 2;
    const int ncol = (lid & 3) << 1;
#pragma unroll
    for (int mt = 0; mt < 4; mt++) {
#pragma unroll
        for (int nt = 0; nt < 4; nt++) {
            float* c0 = Cmn + (size_t)(wm + (mt << 4) + mrow) * H3 + wn + (nt << 3) + ncol;
            *(float2*)c0 = make_float2(acc[mt][nt][0], acc[mt][nt][1]);
            *(float2*)(c0 + 8 * H3) = make_float2(acc[mt][nt][2], acc[mt][nt][3]);
        }
    }
}

// ==================== GEMM wrappers ====================
__global__ __launch_bounds__(512, 1) void pre_gemm_k() {
    __shared__ int rowmap[128];
    int m0 = blockIdx.y << 7;
    if (threadIdx.x < 128) rowmap[threadIdx.x] = m0 + threadIdx.x;
    __syncthreads();
    const __nv_bfloat16* img;
    float* C;
    if (blockIdx.z == 0)      { img = d_img_ihE_s; C = d_GI_s; }
    else if (blockIdx.z == 1) { img = d_img_ihE_a; C = d_GI_a; }
    else                      { img = d_img_ihE_o; C = d_GI_o; }
    int nt = blockIdx.x;
    size_t woff = (size_t)nt * 32 * 32768;  // 32 kchunks per 256-col ntile
    tc_gemm(d_enc_hi, d_enc_lo, E_, 32, img + woff, rowmap, C + (size_t)m0 * H3 + nt * 256);
}

// virtual row layout in d_G (1280 rows x 3072):
//   [0,128) spk gh | [128,256) adr gh | [256,1024) oth gh |
//   [1024,1152) spk ih-state | [1152,1280) adr ih-state
__global__ __launch_bounds__(512, 1) void step_gemm_k(const int* __restrict__ dig, int t) {
    __shared__ int rowmap[128];
    int my = blockIdx.y;
    int m0 = my << 7;
    if (threadIdx.x < 128) {
        int i = threadIdx.x;
        int m = m0 + i;
        int b, role;
        if (m < 256 || m >= 1024) {
            b = i;
            int which = (my == 0) ? 0 : (my == 1) ? 1 : (my == 8) ? 1 : 0;
            role = dig[((size_t)(b * T_ + t)) * 2 + which];
        } else {
            int idx = m - 256;
            b = idx / 6;
            int k = idx % 6;
            int spk = dig[((size_t)(b * T_ + t)) * 2];
            int adr = dig[((size_t)(b * T_ + t)) * 2 + 1];
            int cnt = 0;
            role = 0;
#pragma unroll
            for (int rr = 0; rr < R_; rr++) {
                if (rr != spk && rr != adr) {
                    if (cnt == k) role = rr;
                    cnt++;
                }
            }
        }
        rowmap[i] = (b << 3) + role;
    }
    __syncthreads();
    const __nv_bfloat16* img;
    if (my == 0)      img = d_img_hh_s;
    else if (my == 1) img = d_img_hh_a;
    else if (my < 8)  img = d_img_hh_o;
    else if (my == 8) img = d_img_ihH_s;
    else              img = d_img_ihH_a;
    int nt = blockIdx.x;
    size_t woff = (size_t)nt * 16 * 32768;  // 16 kchunks per ntile
    tc_gemm(d_S_hi, d_S_lo, H_, 16, img + woff, rowmap, d_G + (size_t)m0 * H3 + nt * 256);
}

// ==================== pointwise GRU update ====================
__global__ __launch_bounds__(256) void gru_pointwise(
    float* __restrict__ A, const int* __restrict__ dig, int t,
    const float* __restrict__ bih_s, const float* __restrict__ bhh_s,
    const float* __restrict__ bih_a, const float* __restrict__ bhh_a,
    const float* __restrict__ bih_o, const float* __restrict__ bhh_o) {
    int idx = blockIdx.x * 256 + threadIdx.x;
    int h = idx & (H_ - 1);
    int br = idx >> 10;
    int r = br & 7, b = br >> 3;
    int spk = dig[((size_t)(b * T_ + t)) * 2];
    int adr = dig[((size_t)(b * T_ + t)) * 2 + 1];
    const float *GI, *gihs = nullptr, *bih, *bhh;
    int ghrow;
    if (r == spk) {
        ghrow = b; gihs = d_G + (size_t)(1024 + b) * H3;
        GI = d_GI_s; bih = bih_s; bhh = bhh_s;
    } else if (r == adr) {
        ghrow = 128 + b; gihs = d_G + (size_t)(1152 + b) * H3;
        GI = d_GI_a; bih = bih_a; bhh = bhh_a;
    } else {
        int k = r - (spk < r ? 1 : 0) - (adr < r ? 1 : 0);
        ghrow = 256 + b * 6 + k;
        GI = d_GI_o; bih = bih_o; bhh = bhh_o;
    }
    const float* gi = GI + (size_t)(b * T_ + t) * H3;
    const float* gh = d_G + (size_t)ghrow * H3;
    float gir = gi[h] + bih[h];
    float giz = gi[H_ + h] + bih[H_ + h];
    float gin = gi[2 * H_ + h] + bih[2 * H_ + h];
    if (gihs) {
        gir += gihs[h];
        giz += gihs[H_ + h];
        gin += gihs[2 * H_ + h];
    }
    float ghr = gh[h] + bhh[h];
    float ghz = gh[H_ + h] + bhh[H_ + h];
    float ghn = gh[2 * H_ + h] + bhh[2 * H_ + h];
    float rg = 1.f / (1.f + expf(-(gir + ghr)));
    float zg = 1.f / (1.f + expf(-(giz + ghz)));
    float ng = tanhf(gin + rg * ghn);
    float hold = A[idx];
    float nv = (1.f - zg) * ng + zg * hold;
    A[idx] = nv;
    __nv_bfloat16 hh = __float2bfloat16(nv);
    d_S_hi[idx] = hh;
    d_S_lo[idx] = __float2bfloat16(nv - __bfloat162float(hh));
}

static void* sym_addr(const void* sym) {
    void* p = nullptr;
    cudaGetSymbolAddress(&p, sym);
    return p;
}

extern "C" void kernel_launch(void* const* d_in, const int* in_sizes, int n_in,
                              void* d_out, int out_size) {
    (void)in_sizes; (void)n_in; (void)out_size;
    const float* enc    = (const float*)d_in[0];
    const int*   dig    = (const int*)d_in[1];
    const float* ws_ih  = (const float*)d_in[2];
    const float* ws_hh  = (const float*)d_in[3];
    const float* ws_bih = (const float*)d_in[4];
    const float* ws_bhh = (const float*)d_in[5];
    const float* wa_ih  = (const float*)d_in[6];
    const float* wa_hh  = (const float*)d_in[7];
    const float* wa_bih = (const float*)d_in[8];
    const float* wa_bhh = (const float*)d_in[9];
    const float* wo_ih  = (const float*)d_in[10];
    const float* wo_hh  = (const float*)d_in[11];
    const float* wo_bih = (const float*)d_in[12];
    const float* wo_bhh = (const float*)d_in[13];
    float* A = (float*)d_out;

    cudaFuncSetAttribute(pre_gemm_k, cudaFuncAttributeMaxDynamicSharedMemorySize, SMEM_TOTAL);
    cudaFuncSetAttribute(step_gemm_k, cudaFuncAttributeMaxDynamicSharedMemorySize, SMEM_TOTAL);

    cudaMemsetAsync(d_out, 0, (size_t)B_ * R_ * H_ * sizeof(float), 0);
    cudaMemsetAsync(sym_addr(d_S_hi), 0, (size_t)B_ * R_ * H_ * 2, 0);
    cudaMemsetAsync(sym_addr(d_S_lo), 0, (size_t)B_ * R_ * H_ * 2, 0);

    conv_enc<<<(int)((size_t)B_ * T_ * E_ / 256), 256>>>(enc);
    conv_all<<<dim3(24576, 1, 8), 256>>>(ws_hh, wa_hh, wo_hh, ws_ih, wa_ih, wo_ih);

    // state-independent gi precompute: 12 ntiles x 64 mtiles x 3 matrices
    pre_gemm_k<<<dim3(12, 64, 3), 512, SMEM_TOTAL>>>();

    // sequential scan
    for (int t = 0; t < T_; t++) {
        step_gemm_k<<<dim3(12, 10), 512, SMEM_TOTAL>>>(dig, t);
        gru_pointwise<<<4096, 256>>>(A, dig, t, ws_bih, ws_bhh, wa_bih, wa_bhh,
                                     wo_bih, wo_bhh);
    }
}

// round 5
// speedup vs baseline: 1.1048x; 1.1048x over previous
#include <cuda_runtime.h>
#include <cuda_bf16.h>
#include <cstdint>
#include <math.h>

#define B_ 128
#define T_ 64
#define E_ 2048
#define H_ 1024
#define R_ 8
#define H3 3072

// ==================== helpers (baseline PTX only) ====================
__device__ __forceinline__ uint32_t smem_to_u32(const void* p) {
    uint32_t a;
    asm("{ .reg .u64 t; cvta.to.shared.u64 t, %1; cvt.u32.u64 %0, t; }"
        : "=r"(a) : "l"(p));
    return a;
}
__device__ __forceinline__ uint32_t swz(uint32_t b) { return b ^ ((b >> 3) & 0x70); }

__device__ __forceinline__ void cpa16(uint32_t dst, const void* src) {
    asm volatile("cp.async.cg.shared.global [%0], [%1], 16;" :: "r"(dst), "l"(src));
}
__device__ __forceinline__ void ldm_x4(uint32_t* r, uint32_t a) {
    asm volatile("ldmatrix.sync.aligned.m8n8.x4.shared.b16 {%0,%1,%2,%3}, [%4];"
                 : "=r"(r[0]), "=r"(r[1]), "=r"(r[2]), "=r"(r[3]) : "r"(a));
}
__device__ __forceinline__ void mma16816(float* c, const uint32_t* a, const uint32_t* b) {
    asm volatile(
        "mma.sync.aligned.m16n8k16.row.col.f32.bf16.bf16.f32 "
        "{%0,%1,%2,%3}, {%4,%5,%6,%7}, {%8,%9}, {%0,%1,%2,%3};"
        : "+f"(c[0]), "+f"(c[1]), "+f"(c[2]), "+f"(c[3])
        : "r"(a[0]), "r"(a[1]), "r"(a[2]), "r"(a[3]), "r"(b[0]), "r"(b[1]));
}

// ==================== scratch (static device, allocation-free) ====================
__device__ float d_GI_s[(size_t)B_ * T_ * H3];
__device__ float d_GI_a[(size_t)B_ * T_ * H3];
__device__ float d_GI_o[(size_t)B_ * T_ * H3];
__device__ float d_G[1280 * H3];

__device__ __nv_bfloat16 d_enc_hi[(size_t)B_ * T_ * E_];
__device__ __nv_bfloat16 d_enc_lo[(size_t)B_ * T_ * E_];
__device__ __nv_bfloat16 d_S_hi[(size_t)B_ * R_ * H_];
__device__ __nv_bfloat16 d_S_lo[(size_t)B_ * R_ * H_];

// Weight images: pre-swizzled SMEM chunk tiles.
// Chunk tile = 128 n-rows x 128B row = [k32 hi | k32 lo], SW128-swizzled. 16KB each.
// (n,k,sel) -> nt=n>>7, r=n&127, cc=k>>5, j=k&31:
//   elem = ((nt*KWC + cc) << 13) + swz(r*128 + sel*64 + j*2)/2
__device__ __align__(16) __nv_bfloat16 d_img_hh_s[3072 * 1024 * 2];
__device__ __align__(16) __nv_bfloat16 d_img_hh_a[3072 * 1024 * 2];
__device__ __align__(16) __nv_bfloat16 d_img_hh_o[3072 * 1024 * 2];
__device__ __align__(16) __nv_bfloat16 d_img_ihE_s[3072 * 2048 * 2];
__device__ __align__(16) __nv_bfloat16 d_img_ihE_a[3072 * 2048 * 2];
__device__ __align__(16) __nv_bfloat16 d_img_ihE_o[3072 * 2048 * 2];
__device__ __align__(16) __nv_bfloat16 d_img_ihH_s[3072 * 1024 * 2];
__device__ __align__(16) __nv_bfloat16 d_img_ihH_a[3072 * 1024 * 2];

// ==================== conversion kernels ====================
__global__ void conv_enc(const float* __restrict__ enc) {
    size_t idx = (size_t)blockIdx.x * 256 + threadIdx.x;
    float x = enc[idx];
    __nv_bfloat16 h = __float2bfloat16(x);
    d_enc_hi[idx] = h;
    d_enc_lo[idx] = __float2bfloat16(x - __bfloat162float(h));
}

__device__ __forceinline__ size_t wimg_off(int n, int k, int sel, int kwc) {
    int nt = n >> 7, r = n & 127;
    int cc = k >> 5, j = k & 31;
    uint32_t byte = (uint32_t)((r << 7) + (sel << 6) + (j << 1));
    return (((size_t)(nt * kwc + cc)) << 13) + (swz(byte) >> 1);
}

__global__ void conv_all(const float* __restrict__ ws_hh, const float* __restrict__ wa_hh,
                         const float* __restrict__ wo_hh, const float* __restrict__ ws_ih,
                         const float* __restrict__ wa_ih, const float* __restrict__ wo_ih) {
    int z = blockIdx.z;
    const float* src;
    __nv_bfloat16* img;
    int ld, off, kb;
    switch (z) {
        case 0: src = ws_hh; img = d_img_hh_s;  ld = 1024; off = 0;    kb = 10; break;
        case 1: src = wa_hh; img = d_img_hh_a;  ld = 1024; off = 0;    kb = 10; break;
        case 2: src = wo_hh; img = d_img_hh_o;  ld = 1024; off = 0;    kb = 10; break;
        case 3: src = ws_ih; img = d_img_ihE_s; ld = 3072; off = 0;    kb = 11; break;
        case 4: src = wa_ih; img = d_img_ihE_a; ld = 3072; off = 0;    kb = 11; break;
        case 5: src = wo_ih; img = d_img_ihE_o; ld = 2048; off = 0;    kb = 11; break;
        case 6: src = ws_ih; img = d_img_ihH_s; ld = 3072; off = 2048; kb = 10; break;
        default: src = wa_ih; img = d_img_ihH_a; ld = 3072; off = 2048; kb = 10; break;
    }
    size_t idx = (size_t)blockIdx.x * 256 + threadIdx.x;
    if (idx >= ((size_t)3072 << kb)) return;
    int n = (int)(idx >> kb);
    int k = (int)(idx & ((1 << kb) - 1));
    float x = src[(size_t)n * ld + off + k];
    __nv_bfloat16 h = __float2bfloat16(x);
    __nv_bfloat16 l = __float2bfloat16(x - __bfloat162float(h));
    int kwc = 1 << (kb - 5);
    img[wimg_off(n, k, 0, kwc)] = h;
    img[wimg_off(n, k, 1, kwc)] = l;
}

// ==================== GEMM core: 128x128 tile, k32 chunks, 3-stage ====================
static constexpr int STAGE = 32768;                  // A 16K + W 16K
static constexpr int SMEM_TOTAL = 1024 + 3 * STAGE;  // 99328

__device__ __forceinline__ void load_stage(uint32_t st, const __nv_bfloat16* __restrict__ Ahi,
                                           const __nv_bfloat16* __restrict__ Alo, int astride,
                                           const int* __restrict__ rowmap, int koff,
                                           const __nv_bfloat16* __restrict__ Wchunk, int tid) {
#pragma unroll
    for (int i = 0; i < 4; i++) {
        int lin = tid + (i << 8);
        int row = lin >> 3, seg = lin & 7;
        uint32_t so = swz((uint32_t)((row << 7) + (seg << 4)));
        const __nv_bfloat16* src =
            (seg < 4) ? Ahi + (size_t)rowmap[row] * astride + koff + (seg << 3)
                      : Alo + (size_t)rowmap[row] * astride + koff + ((seg - 4) << 3);
        cpa16(st + so, src);
    }
    const char* ws = (const char*)Wchunk;
#pragma unroll
    for (int i = 0; i < 4; i++) {
        uint32_t o = (uint32_t)((tid + (i << 8)) << 4);
        cpa16(st + 16384 + o, ws + o);
    }
    asm volatile("cp.async.commit_group;" ::: "memory");
}

// C(128x128) = Arows(128 x K) * W(128 x K)^T, hi/lo 3-pass bf16
__device__ void tc_gemm(const __nv_bfloat16* __restrict__ Ahi,
                        const __nv_bfloat16* __restrict__ Alo, int astride, int kchunks,
                        const __nv_bfloat16* __restrict__ Wimg,  // pre-offset to this ntile
                        const int* __restrict__ rowmap, float* __restrict__ Cmn) {
    extern __shared__ char smem[];
    uint32_t sb = smem_to_u32(smem) + 1024;
    const int tid = threadIdx.x;
    const int wid = tid >> 5;
    const int lid = tid & 31;
    const int wm = (wid >> 2) << 6;  // 0 or 64
    const int wn = (wid & 3) << 5;   // 0,32,64,96

    const int a_r = (lid & 7) | (((lid >> 3) & 1) << 3);
    const int a_kb = ((lid >> 4) & 1) << 4;
    const int w_r = (lid & 7) | (((lid >> 4) & 1) << 3);
    const int w_kb = ((lid >> 3) & 1) << 4;

    float acc[4][4][4];
#pragma unroll
    for (int i = 0; i < 4; i++)
#pragma unroll
        for (int j = 0; j < 4; j++)
#pragma unroll
            for (int q = 0; q < 4; q++) acc[i][j][q] = 0.f;

#pragma unroll
    for (int c = 0; c < 2; c++)
        if (c < kchunks)
            load_stage(sb + c * STAGE, Ahi, Alo, astride, rowmap, c << 5,
                       Wimg + ((size_t)c << 13), tid);

    int stage = 0;
    for (int c = 0; c < kchunks; c++) {
        if (c + 1 < kchunks) asm volatile("cp.async.wait_group 1;" ::: "memory");
        else                 asm volatile("cp.async.wait_group 0;" ::: "memory");
        __syncthreads();
        if (c + 2 < kchunks) {
            int ns = stage + 2;
            if (ns >= 3) ns -= 3;
            load_stage(sb + ns * STAGE, Ahi, Alo, astride, rowmap, (c + 2) << 5,
                       Wimg + ((size_t)(c + 2) << 13), tid);
        }
        uint32_t stA = sb + stage * STAGE;
        uint32_t stW = stA + 16384;
#pragma unroll
        for (int ks = 0; ks < 2; ks++) {
            uint32_t wh[8], wl[8];
#pragma unroll
            for (int p = 0; p < 2; p++) {
                uint32_t rowb = (uint32_t)((wn + (p << 4) + w_r) << 7);
                ldm_x4(wh + (p << 2), stW + swz(rowb + (ks << 5) + w_kb));
                ldm_x4(wl + (p << 2), stW + swz(rowb + 64 + (ks << 5) + w_kb));
            }
#pragma unroll
            for (int mt = 0; mt < 4; mt++) {
                uint32_t ah[4], al[4];
                uint32_t rowb = (uint32_t)((wm + (mt << 4) + a_r) << 7);
                ldm_x4(ah, stA + swz(rowb + (ks << 5) + a_kb));
                ldm_x4(al, stA + swz(rowb + 64 + (ks << 5) + a_kb));
#pragma unroll
                for (int nt = 0; nt < 4; nt++) {
                    mma16816(acc[mt][nt], ah, wh + (nt << 1));
                    mma16816(acc[mt][nt], al, wh + (nt << 1));
                    mma16816(acc[mt][nt], ah, wl + (nt << 1));
                }
            }
        }
        if (++stage >= 3) stage = 0;
    }

    // epilogue
    const int mrow = lid >> 2;
    const int ncol = (lid & 3) << 1;
#pragma unroll
    for (int mt = 0; mt < 4; mt++) {
#pragma unroll
        for (int nt = 0; nt < 4; nt++) {
            float* c0 = Cmn + (size_t)(wm + (mt << 4) + mrow) * H3 + wn + (nt << 3) + ncol;
            *(float2*)c0 = make_float2(acc[mt][nt][0], acc[mt][nt][1]);
            *(float2*)(c0 + 8 * H3) = make_float2(acc[mt][nt][2], acc[mt][nt][3]);
        }
    }
}

// ==================== GEMM wrappers ====================
__global__ __launch_bounds__(256, 2) void pre_gemm_k() {
    __shared__ int rowmap[128];
    int m0 = blockIdx.y << 7;
    if (threadIdx.x < 128) rowmap[threadIdx.x] = m0 + threadIdx.x;
    __syncthreads();
    const __nv_bfloat16* img;
    float* C;
    if (blockIdx.z == 0)      { img = d_img_ihE_s; C = d_GI_s; }
    else if (blockIdx.z == 1) { img = d_img_ihE_a; C = d_GI_a; }
    else                      { img = d_img_ihE_o; C = d_GI_o; }
    int nt = blockIdx.x;
    size_t woff = (size_t)nt * 64 * 8192;  // 64 k32-chunks per 128-col ntile
    tc_gemm(d_enc_hi, d_enc_lo, E_, 64, img + woff, rowmap, C + (size_t)m0 * H3 + nt * 128);
}

// virtual row layout in d_G (1280 rows x 3072):
//   [0,128) spk gh | [128,256) adr gh | [256,1024) oth gh |
//   [1024,1152) spk ih-state | [1152,1280) adr ih-state
__global__ __launch_bounds__(256, 2) void step_gemm_k(const int* __restrict__ dig, int t) {
    __shared__ int rowmap[128];
    int my = blockIdx.y;
    int m0 = my << 7;
    if (threadIdx.x < 128) {
        int i = threadIdx.x;
        int m = m0 + i;
        int b, role;
        if (m < 256 || m >= 1024) {
            b = i;
            int which = (my == 0) ? 0 : (my == 1) ? 1 : (my == 8) ? 1 : 0;
            role = dig[((size_t)(b * T_ + t)) * 2 + which];
        } else {
            int idx = m - 256;
            b = idx / 6;
            int k = idx % 6;
            int spk = dig[((size_t)(b * T_ + t)) * 2];
            int adr = dig[((size_t)(b * T_ + t)) * 2 + 1];
            int cnt = 0;
            role = 0;
#pragma unroll
            for (int rr = 0; rr < R_; rr++) {
                if (rr != spk && rr != adr) {
                    if (cnt == k) role = rr;
                    cnt++;
                }
            }
        }
        rowmap[i] = (b << 3) + role;
    }
    __syncthreads();
    const __nv_bfloat16* img;
    if (my == 0)      img = d_img_hh_s;
    else if (my == 1) img = d_img_hh_a;
    else if (my < 8)  img = d_img_hh_o;
    else if (my == 8) img = d_img_ihH_s;
    else              img = d_img_ihH_a;
    int nt = blockIdx.x;
    size_t woff = (size_t)nt * 32 * 8192;  // 32 k32-chunks per ntile
    tc_gemm(d_S_hi, d_S_lo, H_, 32, img + woff, rowmap, d_G + (size_t)m0 * H3 + nt * 128);
}

// ==================== pointwise GRU update (float2) ====================
__global__ __launch_bounds__(256) void gru_pointwise(
    float* __restrict__ A, const int* __restrict__ dig, int t,
    const float* __restrict__ bih_s, const float* __restrict__ bhh_s,
    const float* __restrict__ bih_a, const float* __restrict__ bhh_a,
    const float* __restrict__ bih_o, const float* __restrict__ bhh_o) {
    int i2 = blockIdx.x * 256 + threadIdx.x;  // < B*R*H/2
    int idx = i2 << 1;
    int h = idx & (H_ - 1);
    int br = idx >> 10;
    int r = br & 7, b = br >> 3;
    int spk = dig[((size_t)(b * T_ + t)) * 2];
    int adr = dig[((size_t)(b * T_ + t)) * 2 + 1];
    const float *GI, *gihs = nullptr, *bih, *bhh;
    int ghrow;
    if (r == spk) {
        ghrow = b; gihs = d_G + (size_t)(1024 + b) * H3;
        GI = d_GI_s; bih = bih_s; bhh = bhh_s;
    } else if (r == adr) {
        ghrow = 128 + b; gihs = d_G + (size_t)(1152 + b) * H3;
        GI = d_GI_a; bih = bih_a; bhh = bhh_a;
    } else {
        int k = r - (spk < r ? 1 : 0) - (adr < r ? 1 : 0);
        ghrow = 256 + b * 6 + k;
        GI = d_GI_o; bih = bih_o; bhh = bhh_o;
    }
    const float* gi = GI + (size_t)(b * T_ + t) * H3;
    const float* gh = d_G + (size_t)ghrow * H3;
#pragma unroll
    for (int q = 0; q < 2; q++) {
        int hh_ = h + q;
        float gir = gi[hh_] + bih[hh_];
        float giz = gi[H_ + hh_] + bih[H_ + hh_];
        float gin = gi[2 * H_ + hh_] + bih[2 * H_ + hh_];
        if (gihs) {
            gir += gihs[hh_];
            giz += gihs[H_ + hh_];
            gin += gihs[2 * H_ + hh_];
        }
        float ghr = gh[hh_] + bhh[hh_];
        float ghz = gh[H_ + hh_] + bhh[H_ + hh_];
        float ghn = gh[2 * H_ + hh_] + bhh[2 * H_ + hh_];
        float rg = 1.f / (1.f + expf(-(gir + ghr)));
        float zg = 1.f / (1.f + expf(-(giz + ghz)));
        float ng = tanhf(gin + rg * ghn);
        float hold = A[idx + q];
        float nv = (1.f - zg) * ng + zg * hold;
        A[idx + q] = nv;
        __nv_bfloat16 nh = __float2bfloat16(nv);
        d_S_hi[idx + q] = nh;
        d_S_lo[idx + q] = __float2bfloat16(nv - __bfloat162float(nh));
    }
}

static void* sym_addr(const void* sym) {
    void* p = nullptr;
    cudaGetSymbolAddress(&p, sym);
    return p;
}

extern "C" void kernel_launch(void* const* d_in, const int* in_sizes, int n_in,
                              void* d_out, int out_size) {
    (void)in_sizes; (void)n_in; (void)out_size;
    const float* enc    = (const float*)d_in[0];
    const int*   dig    = (const int*)d_in[1];
    const float* ws_ih  = (const float*)d_in[2];
    const float* ws_hh  = (const float*)d_in[3];
    const float* ws_bih = (const float*)d_in[4];
    const float* ws_bhh = (const float*)d_in[5];
    const float* wa_ih  = (const float*)d_in[6];
    const float* wa_hh  = (const float*)d_in[7];
    const float* wa_bih = (const float*)d_in[8];
    const float* wa_bhh = (const float*)d_in[9];
    const float* wo_ih  = (const float*)d_in[10];
    const float* wo_hh  = (const float*)d_in[11];
    const float* wo_bih = (const float*)d_in[12];
    const float* wo_bhh = (const float*)d_in[13];
    float* A = (float*)d_out;

    cudaFuncSetAttribute(pre_gemm_k, cudaFuncAttributeMaxDynamicSharedMemorySize, SMEM_TOTAL);
    cudaFuncSetAttribute(step_gemm_k, cudaFuncAttributeMaxDynamicSharedMemorySize, SMEM_TOTAL);

    cudaMemsetAsync(d_out, 0, (size_t)B_ * R_ * H_ * sizeof(float), 0);
    cudaMemsetAsync(sym_addr(d_S_hi), 0, (size_t)B_ * R_ * H_ * 2, 0);
    cudaMemsetAsync(sym_addr(d_S_lo), 0, (size_t)B_ * R_ * H_ * 2, 0);

    conv_enc<<<(int)((size_t)B_ * T_ * E_ / 256), 256>>>(enc);
    conv_all<<<dim3(24576, 1, 8), 256>>>(ws_hh, wa_hh, wo_hh, ws_ih, wa_ih, wo_ih);

    // state-independent gi precompute: 24 ntiles x 64 mtiles x 3 matrices
    pre_gemm_k<<<dim3(24, 64, 3), 256, SMEM_TOTAL>>>();

    // sequential scan
    for (int t = 0; t < T_; t++) {
        step_gemm_k<<<dim3(24, 10), 256, SMEM_TOTAL>>>(dig, t);
        gru_pointwise<<<2048, 256>>>(A, dig, t, ws_bih, ws_bhh, wa_bih, wa_bhh,
                                     wo_bih, wo_bhh);
    }
}

// round 6
// speedup vs baseline: 1.5044x; 1.3617x over previous
#include <cuda_runtime.h>
#include <cuda_fp16.h>
#include <cstdint>
#include <math.h>

#define B_ 128
#define T_ 64
#define E_ 2048
#define H_ 1024
#define R_ 8
#define H3 3072

// ==================== helpers (baseline PTX only) ====================
__device__ __forceinline__ uint32_t smem_to_u32(const void* p) {
    uint32_t a;
    asm("{ .reg .u64 t; cvta.to.shared.u64 t, %1; cvt.u32.u64 %0, t; }"
        : "=r"(a) : "l"(p));
    return a;
}
__device__ __forceinline__ uint32_t swz(uint32_t b) { return b ^ ((b >> 3) & 0x70); }

__device__ __forceinline__ void cpa16(uint32_t dst, const void* src) {
    asm volatile("cp.async.cg.shared.global [%0], [%1], 16;" :: "r"(dst), "l"(src));
}
__device__ __forceinline__ void ldm_x4(uint32_t* r, uint32_t a) {
    asm volatile("ldmatrix.sync.aligned.m8n8.x4.shared.b16 {%0,%1,%2,%3}, [%4];"
                 : "=r"(r[0]), "=r"(r[1]), "=r"(r[2]), "=r"(r[3]) : "r"(a));
}
__device__ __forceinline__ void mma16816(float* c, const uint32_t* a, const uint32_t* b) {
    asm volatile(
        "mma.sync.aligned.m16n8k16.row.col.f32.f16.f16.f32 "
        "{%0,%1,%2,%3}, {%4,%5,%6,%7}, {%8,%9}, {%0,%1,%2,%3};"
        : "+f"(c[0]), "+f"(c[1]), "+f"(c[2]), "+f"(c[3])
        : "r"(a[0]), "r"(a[1]), "r"(a[2]), "r"(a[3]), "r"(b[0]), "r"(b[1]));
}

// ==================== scratch (static device, allocation-free) ====================
__device__ float d_GI_s[(size_t)B_ * T_ * H3];
__device__ float d_GI_a[(size_t)B_ * T_ * H3];
__device__ float d_GI_o[(size_t)B_ * T_ * H3];
__device__ float d_G[1280 * H3];

__device__ __half d_enc_hi[(size_t)B_ * T_ * E_];
__device__ __half d_enc_lo[(size_t)B_ * T_ * E_];
__device__ __half d_S_hi[(size_t)B_ * R_ * H_];
__device__ __half d_S_lo[(size_t)B_ * R_ * H_];

// W images (single fp16). Per ntile (128 n-rows) per k32 chunk: an 8KB tile.
// Element (n,k): nt=n>>7, r=n&127, cc=k>>5, j=k&31:
//   byte_pre = ((r>>1)<<7) | ((r&1)<<6) | (j<<1)
//   elem = ((nt*KWC + cc) << 12) + swz(byte_pre)/2
__device__ __align__(16) __half d_img_hh_s[3072 * 1024];
__device__ __align__(16) __half d_img_hh_a[3072 * 1024];
__device__ __align__(16) __half d_img_hh_o[3072 * 1024];
__device__ __align__(16) __half d_img_ihE_s[3072 * 2048];
__device__ __align__(16) __half d_img_ihE_a[3072 * 2048];
__device__ __align__(16) __half d_img_ihE_o[3072 * 2048];
__device__ __align__(16) __half d_img_ihH_s[3072 * 1024];
__device__ __align__(16) __half d_img_ihH_a[3072 * 1024];

// ==================== conversion kernels ====================
__global__ void conv_enc(const float* __restrict__ enc) {
    size_t idx = (size_t)blockIdx.x * 256 + threadIdx.x;
    float x = enc[idx];
    __half h = __float2half_rn(x);
    d_enc_hi[idx] = h;
    d_enc_lo[idx] = __float2half_rn(x - __half2float(h));
}

__device__ __forceinline__ size_t wimg_off(int n, int k, int kwc) {
    int nt = n >> 7, r = n & 127;
    int cc = k >> 5, j = k & 31;
    uint32_t byte = (uint32_t)(((r >> 1) << 7) | ((r & 1) << 6) | (j << 1));
    return (((size_t)(nt * kwc + cc)) << 12) + (swz(byte) >> 1);
}

__global__ void conv_all(const float* __restrict__ ws_hh, const float* __restrict__ wa_hh,
                         const float* __restrict__ wo_hh, const float* __restrict__ ws_ih,
                         const float* __restrict__ wa_ih, const float* __restrict__ wo_ih) {
    int z = blockIdx.z;
    const float* src;
    __half* img;
    int ld, off, kb;
    switch (z) {
        case 0: src = ws_hh; img = d_img_hh_s;  ld = 1024; off = 0;    kb = 10; break;
        case 1: src = wa_hh; img = d_img_hh_a;  ld = 1024; off = 0;    kb = 10; break;
        case 2: src = wo_hh; img = d_img_hh_o;  ld = 1024; off = 0;    kb = 10; break;
        case 3: src = ws_ih; img = d_img_ihE_s; ld = 3072; off = 0;    kb = 11; break;
        case 4: src = wa_ih; img = d_img_ihE_a; ld = 3072; off = 0;    kb = 11; break;
        case 5: src = wo_ih; img = d_img_ihE_o; ld = 2048; off = 0;    kb = 11; break;
        case 6: src = ws_ih; img = d_img_ihH_s; ld = 3072; off = 2048; kb = 10; break;
        default: src = wa_ih; img = d_img_ihH_a; ld = 3072; off = 2048; kb = 10; break;
    }
    size_t idx = (size_t)blockIdx.x * 256 + threadIdx.x;
    if (idx >= ((size_t)3072 << kb)) return;
    int n = (int)(idx >> kb);
    int k = (int)(idx & ((1 << kb) - 1));
    float x = src[(size_t)n * ld + off + k];
    img[wimg_off(n, k, 1 << (kb - 5))] = __float2half_rn(x);
}

// ==================== GEMM core: 128x128 tile, k32 chunks, 4-stage ====================
static constexpr int STAGE = 24576;                  // A 16K + W 8K
static constexpr int SMEM_TOTAL = 1024 + 4 * STAGE;  // 99328

__device__ __forceinline__ void load_stage(uint32_t st, const __half* __restrict__ Ahi,
                                           const __half* __restrict__ Alo, int astride,
                                           const int* __restrict__ rowmap, int koff,
                                           const __half* __restrict__ Wchunk, int tid) {
#pragma unroll
    for (int i = 0; i < 4; i++) {
        int lin = tid + (i << 8);
        int row = lin >> 3, seg = lin & 7;
        uint32_t so = swz((uint32_t)((row << 7) + (seg << 4)));
        const __half* src =
            (seg < 4) ? Ahi + (size_t)rowmap[row] * astride + koff + (seg << 3)
                      : Alo + (size_t)rowmap[row] * astride + koff + ((seg - 4) << 3);
        cpa16(st + so, src);
    }
    const char* ws = (const char*)Wchunk;
#pragma unroll
    for (int i = 0; i < 2; i++) {
        uint32_t o = (uint32_t)((tid + (i << 8)) << 4);
        cpa16(st + 16384 + o, ws + o);
    }
    asm volatile("cp.async.commit_group;" ::: "memory");
}

// C(128x128) = Arows(128 x K) * W(128 x K)^T, fp16 2-pass (A split hi/lo, W single)
__device__ void tc_gemm(const __half* __restrict__ Ahi, const __half* __restrict__ Alo,
                        int astride, int kchunks,
                        const __half* __restrict__ Wimg,  // pre-offset to this ntile
                        const int* __restrict__ rowmap, float* __restrict__ Cmn) {
    extern __shared__ char smem[];
    uint32_t sb = smem_to_u32(smem) + 1024;
    const int tid = threadIdx.x;
    const int wid = tid >> 5;
    const int lid = tid & 31;
    const int wm = (wid >> 2) << 6;  // 0 or 64
    const int wn = (wid & 3) << 5;   // 0,32,64,96

    const int a_r = (lid & 7) | (((lid >> 3) & 1) << 3);
    const int a_kb = ((lid >> 4) & 1) << 4;
    const int w_r = (lid & 7) | (((lid >> 4) & 1) << 3);
    const int w_kb = ((lid >> 3) & 1) << 4;

    float acc[4][4][4];
#pragma unroll
    for (int i = 0; i < 4; i++)
#pragma unroll
        for (int j = 0; j < 4; j++)
#pragma unroll
            for (int q = 0; q < 4; q++) acc[i][j][q] = 0.f;

#pragma unroll
    for (int c = 0; c < 3; c++)
        if (c < kchunks)
            load_stage(sb + c * STAGE, Ahi, Alo, astride, rowmap, c << 5,
                       Wimg + ((size_t)c << 12), tid);

    for (int c = 0; c < kchunks; c++) {
        int rem = kchunks - 1 - c;
        if (rem >= 2)      asm volatile("cp.async.wait_group 2;" ::: "memory");
        else if (rem == 1) asm volatile("cp.async.wait_group 1;" ::: "memory");
        else               asm volatile("cp.async.wait_group 0;" ::: "memory");
        __syncthreads();
        if (c + 3 < kchunks)
            load_stage(sb + ((c + 3) & 3) * STAGE, Ahi, Alo, astride, rowmap, (c + 3) << 5,
                       Wimg + ((size_t)(c + 3) << 12), tid);

        uint32_t stA = sb + (c & 3) * STAGE;
        uint32_t stW = stA + 16384;
#pragma unroll
        for (int ks = 0; ks < 2; ks++) {
            uint32_t wh[8];
#pragma unroll
            for (int p = 0; p < 2; p++) {
                int row = wn + (p << 4) + w_r;
                uint32_t bp = (uint32_t)(((row >> 1) << 7) + ((row & 1) << 6) +
                                         (ks << 5) + w_kb);
                ldm_x4(wh + (p << 2), stW + swz(bp));
            }
#pragma unroll
            for (int mt = 0; mt < 4; mt++) {
                uint32_t ah[4], al[4];
                uint32_t rowb = (uint32_t)((wm + (mt << 4) + a_r) << 7);
                ldm_x4(ah, stA + swz(rowb + (ks << 5) + a_kb));
                ldm_x4(al, stA + swz(rowb + 64 + (ks << 5) + a_kb));
#pragma unroll
                for (int nt = 0; nt < 4; nt++) {
                    mma16816(acc[mt][nt], ah, wh + (nt << 1));
                    mma16816(acc[mt][nt], al, wh + (nt << 1));
                }
            }
        }
    }

    // epilogue
    const int mrow = lid >> 2;
    const int ncol = (lid & 3) << 1;
#pragma unroll
    for (int mt = 0; mt < 4; mt++) {
#pragma unroll
        for (int nt = 0; nt < 4; nt++) {
            float* c0 = Cmn + (size_t)(wm + (mt << 4) + mrow) * H3 + wn + (nt << 3) + ncol;
            *(float2*)c0 = make_float2(acc[mt][nt][0], acc[mt][nt][1]);
            *(float2*)(c0 + 8 * H3) = make_float2(acc[mt][nt][2], acc[mt][nt][3]);
        }
    }
}

// ==================== GEMM wrappers ====================
__global__ __launch_bounds__(256, 2) void pre_gemm_k() {
    __shared__ int rowmap[128];
    int m0 = blockIdx.y << 7;
    if (threadIdx.x < 128) rowmap[threadIdx.x] = m0 + threadIdx.x;
    __syncthreads();
    const __half* img;
    float* C;
    if (blockIdx.z == 0)      { img = d_img_ihE_s; C = d_GI_s; }
    else if (blockIdx.z == 1) { img = d_img_ihE_a; C = d_GI_a; }
    else                      { img = d_img_ihE_o; C = d_GI_o; }
    int nt = blockIdx.x;
    size_t woff = (size_t)nt * 64 * 4096;  // 64 k32-chunks per 128-col ntile
    tc_gemm(d_enc_hi, d_enc_lo, E_, 64, img + woff, rowmap, C + (size_t)m0 * H3 + nt * 128);
}

// virtual row layout in d_G (1280 rows x 3072):
//   [0,128) spk gh | [128,256) adr gh | [256,1024) oth gh |
//   [1024,1152) spk ih-state | [1152,1280) adr ih-state
__global__ __launch_bounds__(256, 2) void step_gemm_k(const int* __restrict__ dig, int t) {
    __shared__ int rowmap[128];
    int my = blockIdx.y;
    int m0 = my << 7;
    if (threadIdx.x < 128) {
        int i = threadIdx.x;
        int m = m0 + i;
        int b, role;
        if (m < 256 || m >= 1024) {
            b = i;
            int which = (my == 0) ? 0 : (my == 1) ? 1 : (my == 8) ? 1 : 0;
            role = dig[((size_t)(b * T_ + t)) * 2 + which];
        } else {
            int idx = m - 256;
            b = idx / 6;
            int k = idx % 6;
            int spk = dig[((size_t)(b * T_ + t)) * 2];
            int adr = dig[((size_t)(b * T_ + t)) * 2 + 1];
            int cnt = 0;
            role = 0;
#pragma unroll
            for (int rr = 0; rr < R_; rr++) {
                if (rr != spk && rr != adr) {
                    if (cnt == k) role = rr;
                    cnt++;
                }
            }
        }
        rowmap[i] = (b << 3) + role;
    }
    __syncthreads();
    const __half* img;
    if (my == 0)      img = d_img_hh_s;
    else if (my == 1) img = d_img_hh_a;
    else if (my < 8)  img = d_img_hh_o;
    else if (my == 8) img = d_img_ihH_s;
    else              img = d_img_ihH_a;
    int nt = blockIdx.x;
    size_t woff = (size_t)nt * 32 * 4096;  // 32 k32-chunks per ntile
    tc_gemm(d_S_hi, d_S_lo, H_, 32, img + woff, rowmap, d_G + (size_t)m0 * H3 + nt * 128);
}

// ==================== pointwise GRU update (float2) ====================
__global__ __launch_bounds__(256) void gru_pointwise(
    float* __restrict__ A, const int* __restrict__ dig, int t,
    const float* __restrict__ bih_s, const float* __restrict__ bhh_s,
    const float* __restrict__ bih_a, const float* __restrict__ bhh_a,
    const float* __restrict__ bih_o, const float* __restrict__ bhh_o) {
    int i2 = blockIdx.x * 256 + threadIdx.x;  // < B*R*H/2
    int idx = i2 << 1;
    int h = idx & (H_ - 1);
    int br = idx >> 10;
    int r = br & 7, b = br >> 3;
    int spk = dig[((size_t)(b * T_ + t)) * 2];
    int adr = dig[((size_t)(b * T_ + t)) * 2 + 1];
    const float *GI, *gihs = nullptr, *bih, *bhh;
    int ghrow;
    if (r == spk) {
        ghrow = b; gihs = d_G + (size_t)(1024 + b) * H3;
        GI = d_GI_s; bih = bih_s; bhh = bhh_s;
    } else if (r == adr) {
        ghrow = 128 + b; gihs = d_G + (size_t)(1152 + b) * H3;
        GI = d_GI_a; bih = bih_a; bhh = bhh_a;
    } else {
        int k = r - (spk < r ? 1 : 0) - (adr < r ? 1 : 0);
        ghrow = 256 + b * 6 + k;
        GI = d_GI_o; bih = bih_o; bhh = bhh_o;
    }
    const float* gi = GI + (size_t)(b * T_ + t) * H3;
    const float* gh = d_G + (size_t)ghrow * H3;
#pragma unroll
    for (int q = 0; q < 2; q++) {
        int hh_ = h + q;
        float gir = gi[hh_] + bih[hh_];
        float giz = gi[H_ + hh_] + bih[H_ + hh_];
        float gin = gi[2 * H_ + hh_] + bih[2 * H_ + hh_];
        if (gihs) {
            gir += gihs[hh_];
            giz += gihs[H_ + hh_];
            gin += gihs[2 * H_ + hh_];
        }
        float ghr = gh[hh_] + bhh[hh_];
        float ghz = gh[H_ + hh_] + bhh[H_ + hh_];
        float ghn = gh[2 * H_ + hh_] + bhh[2 * H_ + hh_];
        float rg = 1.f / (1.f + expf(-(gir + ghr)));
        float zg = 1.f / (1.f + expf(-(giz + ghz)));
        float ng = tanhf(gin + rg * ghn);
        float hold = A[idx + q];
        float nv = (1.f - zg) * ng + zg * hold;
        A[idx + q] = nv;
        __half nh = __float2half_rn(nv);
        d_S_hi[idx + q] = nh;
        d_S_lo[idx + q] = __float2half_rn(nv - __half2float(nh));
    }
}

static void* sym_addr(const void* sym) {
    void* p = nullptr;
    cudaGetSymbolAddress(&p, sym);
    return p;
}

extern "C" void kernel_launch(void* const* d_in, const int* in_sizes, int n_in,
                              void* d_out, int out_size) {
    (void)in_sizes; (void)n_in; (void)out_size;
    const float* enc    = (const float*)d_in[0];
    const int*   dig    = (const int*)d_in[1];
    const float* ws_ih  = (const float*)d_in[2];
    const float* ws_hh  = (const float*)d_in[3];
    const float* ws_bih = (const float*)d_in[4];
    const float* ws_bhh = (const float*)d_in[5];
    const float* wa_ih  = (const float*)d_in[6];
    const float* wa_hh  = (const float*)d_in[7];
    const float* wa_bih = (const float*)d_in[8];
    const float* wa_bhh = (const float*)d_in[9];
    const float* wo_ih  = (const float*)d_in[10];
    const float* wo_hh  = (const float*)d_in[11];
    const float* wo_bih = (const float*)d_in[12];
    const float* wo_bhh = (const float*)d_in[13];
    float* A = (float*)d_out;

    cudaFuncSetAttribute(pre_gemm_k, cudaFuncAttributeMaxDynamicSharedMemorySize, SMEM_TOTAL);
    cudaFuncSetAttribute(step_gemm_k, cudaFuncAttributeMaxDynamicSharedMemorySize, SMEM_TOTAL);

    cudaMemsetAsync(d_out, 0, (size_t)B_ * R_ * H_ * sizeof(float), 0);
    cudaMemsetAsync(sym_addr(d_S_hi), 0, (size_t)B_ * R_ * H_ * 2, 0);
    cudaMemsetAsync(sym_addr(d_S_lo), 0, (size_t)B_ * R_ * H_ * 2, 0);

    conv_enc<<<(int)((size_t)B_ * T_ * E_ / 256), 256>>>(enc);
    conv_all<<<dim3(24576, 1, 8), 256>>>(ws_hh, wa_hh, wo_hh, ws_ih, wa_ih, wo_ih);

    // state-independent gi precompute: 24 ntiles x 64 mtiles x 3 matrices
    pre_gemm_k<<<dim3(24, 64, 3), 256, SMEM_TOTAL>>>();

    // sequential scan
    for (int t = 0; t < T_; t++) {
        step_gemm_k<<<dim3(24, 10), 256, SMEM_TOTAL>>>(dig, t);
        gru_pointwise<<<2048, 256>>>(A, dig, t, ws_bih, ws_bhh, wa_bih, wa_bhh,
                                     wo_bih, wo_bhh);
    }
}

// round 7
// speedup vs baseline: 2.5973x; 1.7264x over previous
#include <cuda_runtime.h>
#include <cuda_fp16.h>
#include <cstdint>
#include <math.h>

#define B_ 128
#define T_ 64
#define E_ 2048
#define H_ 1024
#define R_ 8
#define H3 3072

// ==================== helpers (baseline PTX only) ====================
__device__ __forceinline__ uint32_t smem_to_u32(const void* p) {
    uint32_t a;
    asm("{ .reg .u64 t; cvta.to.shared.u64 t, %1; cvt.u32.u64 %0, t; }"
        : "=r"(a) : "l"(p));
    return a;
}
__device__ __forceinline__ uint32_t swz(uint32_t b) { return b ^ ((b >> 3) & 0x70); }

__device__ __forceinline__ void cpa16(uint32_t dst, const void* src) {
    asm volatile("cp.async.cg.shared.global [%0], [%1], 16;" :: "r"(dst), "l"(src));
}
__device__ __forceinline__ void ldm_x4(uint32_t* r, uint32_t a) {
    asm volatile("ldmatrix.sync.aligned.m8n8.x4.shared.b16 {%0,%1,%2,%3}, [%4];"
                 : "=r"(r[0]), "=r"(r[1]), "=r"(r[2]), "=r"(r[3]) : "r"(a));
}
__device__ __forceinline__ void mma16816(float* c, const uint32_t* a, const uint32_t* b) {
    asm volatile(
        "mma.sync.aligned.m16n8k16.row.col.f32.f16.f16.f32 "
        "{%0,%1,%2,%3}, {%4,%5,%6,%7}, {%8,%9}, {%0,%1,%2,%3};"
        : "+f"(c[0]), "+f"(c[1]), "+f"(c[2]), "+f"(c[3])
        : "r"(a[0]), "r"(a[1]), "r"(a[2]), "r"(a[3]), "r"(b[0]), "r"(b[1]));
}

// ==================== scratch (static device, allocation-free) ====================
__device__ float d_GI_s[(size_t)B_ * T_ * H3];
__device__ float d_GI_a[(size_t)B_ * T_ * H3];
__device__ float d_GI_o[(size_t)B_ * T_ * H3];
__device__ float d_G[1280 * H3];

__device__ __half d_enc_h[(size_t)B_ * T_ * E_];
__device__ __half d_S_h[(size_t)B_ * R_ * H_];

// W images (fp16). Per ntile (128 n-rows) per k64 chunk: a 16KB SW128 tile.
// Element (n,k): nt=n>>7, r=n&127, cc=k>>6, j=k&63:
//   elem = ((nt*KWC + cc) << 13) + swz(r*128 + j*2)/2
__device__ __align__(16) __half d_img_hh_s[3072 * 1024];
__device__ __align__(16) __half d_img_hh_a[3072 * 1024];
__device__ __align__(16) __half d_img_hh_o[3072 * 1024];
__device__ __align__(16) __half d_img_ihE_s[3072 * 2048];
__device__ __align__(16) __half d_img_ihE_a[3072 * 2048];
__device__ __align__(16) __half d_img_ihE_o[3072 * 2048];
__device__ __align__(16) __half d_img_ihH_s[3072 * 1024];
__device__ __align__(16) __half d_img_ihH_a[3072 * 1024];

// ==================== conversion kernels ====================
__global__ void conv_enc(const float* __restrict__ enc) {
    size_t idx = (size_t)blockIdx.x * 256 + threadIdx.x;
    d_enc_h[idx] = __float2half_rn(enc[idx]);
}

__device__ __forceinline__ size_t wimg_off(int n, int k, int kwc) {
    int nt = n >> 7, r = n & 127;
    int cc = k >> 6, j = k & 63;
    uint32_t byte = (uint32_t)((r << 7) + (j << 1));
    return (((size_t)(nt * kwc + cc)) << 13) + (swz(byte) >> 1);
}

__global__ void conv_all(const float* __restrict__ ws_hh, const float* __restrict__ wa_hh,
                         const float* __restrict__ wo_hh, const float* __restrict__ ws_ih,
                         const float* __restrict__ wa_ih, const float* __restrict__ wo_ih) {
    int z = blockIdx.z;
    const float* src;
    __half* img;
    int ld, off, kb;
    switch (z) {
        case 0: src = ws_hh; img = d_img_hh_s;  ld = 1024; off = 0;    kb = 10; break;
        case 1: src = wa_hh; img = d_img_hh_a;  ld = 1024; off = 0;    kb = 10; break;
        case 2: src = wo_hh; img = d_img_hh_o;  ld = 1024; off = 0;    kb = 10; break;
        case 3: src = ws_ih; img = d_img_ihE_s; ld = 3072; off = 0;    kb = 11; break;
        case 4: src = wa_ih; img = d_img_ihE_a; ld = 3072; off = 0;    kb = 11; break;
        case 5: src = wo_ih; img = d_img_ihE_o; ld = 2048; off = 0;    kb = 11; break;
        case 6: src = ws_ih; img = d_img_ihH_s; ld = 3072; off = 2048; kb = 10; break;
        default: src = wa_ih; img = d_img_ihH_a; ld = 3072; off = 2048; kb = 10; break;
    }
    size_t idx = (size_t)blockIdx.x * 256 + threadIdx.x;
    if (idx >= ((size_t)3072 << kb)) return;
    int n = (int)(idx >> kb);
    int k = (int)(idx & ((1 << kb) - 1));
    float x = src[(size_t)n * ld + off + k];
    img[wimg_off(n, k, 1 << (kb - 6))] = __float2half_rn(x);
}

// ==================== GEMM core: 128x128 tile, k64 chunks, 3-stage ====================
static constexpr int STAGE = 32768;                  // A 16K + W 16K
static constexpr int SMEM_TOTAL = 1024 + 3 * STAGE;  // 99328

__device__ __forceinline__ void load_stage(uint32_t st, const __half* __restrict__ Ah,
                                           int astride, const int* __restrict__ rowmap,
                                           int koff, const __half* __restrict__ Wchunk,
                                           int tid) {
#pragma unroll
    for (int i = 0; i < 4; i++) {
        int lin = tid + (i << 8);
        int row = lin >> 3, seg = lin & 7;
        uint32_t so = swz((uint32_t)((row << 7) + (seg << 4)));
        cpa16(st + so, Ah + (size_t)rowmap[row] * astride + koff + (seg << 3));
    }
    const char* ws = (const char*)Wchunk;
#pragma unroll
    for (int i = 0; i < 4; i++) {
        uint32_t o = (uint32_t)((tid + (i << 8)) << 4);
        cpa16(st + 16384 + o, ws + o);
    }
    asm volatile("cp.async.commit_group;" ::: "memory");
}

// C(128x128) = Arows(128 x K) * W(128 x K)^T, single-pass fp16
__device__ void tc_gemm(const __half* __restrict__ Ah, int astride, int kchunks,
                        const __half* __restrict__ Wimg,  // pre-offset to this ntile
                        const int* __restrict__ rowmap, float* __restrict__ Cmn) {
    extern __shared__ char smem[];
    uint32_t sb = smem_to_u32(smem) + 1024;
    const int tid = threadIdx.x;
    const int wid = tid >> 5;
    const int lid = tid & 31;
    const int wm = (wid >> 2) << 6;  // 0 or 64
    const int wn = (wid & 3) << 5;   // 0,32,64,96

    const int a_r = (lid & 7) | (((lid >> 3) & 1) << 3);
    const int a_kb = ((lid >> 4) & 1) << 4;
    const int w_r = (lid & 7) | (((lid >> 4) & 1) << 3);
    const int w_kb = ((lid >> 3) & 1) << 4;

    float acc[4][4][4];
#pragma unroll
    for (int i = 0; i < 4; i++)
#pragma unroll
        for (int j = 0; j < 4; j++)
#pragma unroll
            for (int q = 0; q < 4; q++) acc[i][j][q] = 0.f;

#pragma unroll
    for (int c = 0; c < 2; c++)
        if (c < kchunks)
            load_stage(sb + c * STAGE, Ah, astride, rowmap, c << 6,
                       Wimg + ((size_t)c << 13), tid);

    int stage = 0;
    for (int c = 0; c < kchunks; c++) {
        if (c + 1 < kchunks) asm volatile("cp.async.wait_group 1;" ::: "memory");
        else                 asm volatile("cp.async.wait_group 0;" ::: "memory");
        __syncthreads();
        if (c + 2 < kchunks) {
            int ns = stage + 2;
            if (ns >= 3) ns -= 3;
            load_stage(sb + ns * STAGE, Ah, astride, rowmap, (c + 2) << 6,
                       Wimg + ((size_t)(c + 2) << 13), tid);
        }
        uint32_t stA = sb + stage * STAGE;
        uint32_t stW = stA + 16384;
#pragma unroll
        for (int ks = 0; ks < 4; ks++) {
            uint32_t wf[8];
#pragma unroll
            for (int p = 0; p < 2; p++) {
                uint32_t rowb = (uint32_t)((wn + (p << 4) + w_r) << 7);
                ldm_x4(wf + (p << 2), stW + swz(rowb + (ks << 5) + w_kb));
            }
#pragma unroll
            for (int mt = 0; mt < 4; mt++) {
                uint32_t af[4];
                uint32_t rowb = (uint32_t)((wm + (mt << 4) + a_r) << 7);
                ldm_x4(af, stA + swz(rowb + (ks << 5) + a_kb));
#pragma unroll
                for (int nt = 0; nt < 4; nt++)
                    mma16816(acc[mt][nt], af, wf + (nt << 1));
            }
        }
        if (++stage >= 3) stage = 0;
    }

    // epilogue
    const int mrow = lid >> 2;
    const int ncol = (lid & 3) << 1;
#pragma unroll
    for (int mt = 0; mt < 4; mt++) {
#pragma unroll
        for (int nt = 0; nt < 4; nt++) {
            float* c0 = Cmn + (size_t)(wm + (mt << 4) + mrow) * H3 + wn + (nt << 3) + ncol;
            *(float2*)c0 = make_float2(acc[mt][nt][0], acc[mt][nt][1]);
            *(float2*)(c0 + 8 * H3) = make_float2(acc[mt][nt][2], acc[mt][nt][3]);
        }
    }
}

// ==================== GEMM wrappers ====================
__global__ __launch_bounds__(256, 2) void pre_gemm_k() {
    __shared__ int rowmap[128];
    int m0 = blockIdx.y << 7;
    if (threadIdx.x < 128) rowmap[threadIdx.x] = m0 + threadIdx.x;
    __syncthreads();
    const __half* img;
    float* C;
    if (blockIdx.z == 0)      { img = d_img_ihE_s; C = d_GI_s; }
    else if (blockIdx.z == 1) { img = d_img_ihE_a; C = d_GI_a; }
    else                      { img = d_img_ihE_o; C = d_GI_o; }
    int nt = blockIdx.x;
    size_t woff = (size_t)nt * 32 * 8192;  // 32 k64-chunks per 128-col ntile
    tc_gemm(d_enc_h, E_, 32, img + woff, rowmap, C + (size_t)m0 * H3 + nt * 128);
}

// virtual row layout in d_G (1280 rows x 3072):
//   [0,128) spk gh | [128,256) adr gh | [256,1024) oth gh |
//   [1024,1152) spk ih-state | [1152,1280) adr ih-state
__global__ __launch_bounds__(256, 2) void step_gemm_k(const int* __restrict__ dig, int t) {
    __shared__ int rowmap[128];
    int my = blockIdx.y;
    int m0 = my << 7;
    if (threadIdx.x < 128) {
        int i = threadIdx.x;
        int m = m0 + i;
        int b, role;
        if (m < 256 || m >= 1024) {
            b = i;
            int which = (my == 0) ? 0 : (my == 1) ? 1 : (my == 8) ? 1 : 0;
            role = dig[((size_t)(b * T_ + t)) * 2 + which];
        } else {
            int idx = m - 256;
            b = idx / 6;
            int k = idx % 6;
            int spk = dig[((size_t)(b * T_ + t)) * 2];
            int adr = dig[((size_t)(b * T_ + t)) * 2 + 1];
            int cnt = 0;
            role = 0;
#pragma unroll
            for (int rr = 0; rr < R_; rr++) {
                if (rr != spk && rr != adr) {
                    if (cnt == k) role = rr;
                    cnt++;
                }
            }
        }
        rowmap[i] = (b << 3) + role;
    }
    __syncthreads();
    const __half* img;
    if (my == 0)      img = d_img_hh_s;
    else if (my == 1) img = d_img_hh_a;
    else if (my < 8)  img = d_img_hh_o;
    else if (my == 8) img = d_img_ihH_s;
    else              img = d_img_ihH_a;
    int nt = blockIdx.x;
    size_t woff = (size_t)nt * 16 * 8192;  // 16 k64-chunks per ntile
    tc_gemm(d_S_h, H_, 16, img + woff, rowmap, d_G + (size_t)m0 * H3 + nt * 128);
}

// ==================== pointwise GRU update (float4) ====================
__global__ __launch_bounds__(512) void gru_pointwise(
    float* __restrict__ A, const int* __restrict__ dig, int t,
    const float* __restrict__ bih_s, const float* __restrict__ bhh_s,
    const float* __restrict__ bih_a, const float* __restrict__ bhh_a,
    const float* __restrict__ bih_o, const float* __restrict__ bhh_o) {
    int i4 = blockIdx.x * 512 + threadIdx.x;  // < B*R*H/4
    int idx = i4 << 2;
    int h = idx & (H_ - 1);
    int br = idx >> 10;
    int r = br & 7, b = br >> 3;
    int spk = dig[((size_t)(b * T_ + t)) * 2];
    int adr = dig[((size_t)(b * T_ + t)) * 2 + 1];
    const float *GI, *gihs = nullptr, *bih, *bhh;
    int ghrow;
    if (r == spk) {
        ghrow = b; gihs = d_G + (size_t)(1024 + b) * H3;
        GI = d_GI_s; bih = bih_s; bhh = bhh_s;
    } else if (r == adr) {
        ghrow = 128 + b; gihs = d_G + (size_t)(1152 + b) * H3;
        GI = d_GI_a; bih = bih_a; bhh = bhh_a;
    } else {
        int k = r - (spk < r ? 1 : 0) - (adr < r ? 1 : 0);
        ghrow = 256 + b * 6 + k;
        GI = d_GI_o; bih = bih_o; bhh = bhh_o;
    }
    const float* gi = GI + (size_t)(b * T_ + t) * H3 + h;
    const float* gh = d_G + (size_t)ghrow * H3 + h;
    float4 gir = *(const float4*)(gi);
    float4 giz = *(const float4*)(gi + H_);
    float4 gin = *(const float4*)(gi + 2 * H_);
    if (gihs) {
        const float* gs = gihs + h;
        float4 s0 = *(const float4*)(gs);
        float4 s1 = *(const float4*)(gs + H_);
        float4 s2 = *(const float4*)(gs + 2 * H_);
        gir.x += s0.x; gir.y += s0.y; gir.z += s0.z; gir.w += s0.w;
        giz.x += s1.x; giz.y += s1.y; giz.z += s1.z; giz.w += s1.w;
        gin.x += s2.x; gin.y += s2.y; gin.z += s2.z; gin.w += s2.w;
    }
    float4 ghr = *(const float4*)(gh);
    float4 ghz = *(const float4*)(gh + H_);
    float4 ghn = *(const float4*)(gh + 2 * H_);
    float4 b0 = *(const float4*)(bih + h);
    float4 b1 = *(const float4*)(bih + H_ + h);
    float4 b2 = *(const float4*)(bih + 2 * H_ + h);
    float4 c0 = *(const float4*)(bhh + h);
    float4 c1 = *(const float4*)(bhh + H_ + h);
    float4 c2 = *(const float4*)(bhh + 2 * H_ + h);
    float4 hold = *(const float4*)(A + idx);
    float out[4];
    __half outh[4];
#pragma unroll
    for (int q = 0; q < 4; q++) {
        float vr = ((&gir.x)[q] + (&b0.x)[q]) + ((&ghr.x)[q] + (&c0.x)[q]);
        float vz = ((&giz.x)[q] + (&b1.x)[q]) + ((&ghz.x)[q] + (&c1.x)[q]);
        float hn = (&ghn.x)[q] + (&c2.x)[q];
        float rg = 1.f / (1.f + expf(-vr));
        float zg = 1.f / (1.f + expf(-vz));
        float ng = tanhf((&gin.x)[q] + (&b2.x)[q] + rg * hn);
        float nv = (1.f - zg) * ng + zg * (&hold.x)[q];
        out[q] = nv;
        outh[q] = __float2half_rn(nv);
    }
    *(float4*)(A + idx) = make_float4(out[0], out[1], out[2], out[3]);
    *(uint2*)(&d_S_h[idx]) = *(uint2*)outh;
}

static void* sym_addr(const void* sym) {
    void* p = nullptr;
    cudaGetSymbolAddress(&p, sym);
    return p;
}

extern "C" void kernel_launch(void* const* d_in, const int* in_sizes, int n_in,
                              void* d_out, int out_size) {
    (void)in_sizes; (void)n_in; (void)out_size;
    const float* enc    = (const float*)d_in[0];
    const int*   dig    = (const int*)d_in[1];
    const float* ws_ih  = (const float*)d_in[2];
    const float* ws_hh  = (const float*)d_in[3];
    const float* ws_bih = (const float*)d_in[4];
    const float* ws_bhh = (const float*)d_in[5];
    const float* wa_ih  = (const float*)d_in[6];
    const float* wa_hh  = (const float*)d_in[7];
    const float* wa_bih = (const float*)d_in[8];
    const float* wa_bhh = (const float*)d_in[9];
    const float* wo_ih  = (const float*)d_in[10];
    const float* wo_hh  = (const float*)d_in[11];
    const float* wo_bih = (const float*)d_in[12];
    const float* wo_bhh = (const float*)d_in[13];
    float* A = (float*)d_out;

    cudaFuncSetAttribute(pre_gemm_k, cudaFuncAttributeMaxDynamicSharedMemorySize, SMEM_TOTAL);
    cudaFuncSetAttribute(step_gemm_k, cudaFuncAttributeMaxDynamicSharedMemorySize, SMEM_TOTAL);

    cudaMemsetAsync(d_out, 0, (size_t)B_ * R_ * H_ * sizeof(float), 0);
    cudaMemsetAsync(sym_addr(d_S_h), 0, (size_t)B_ * R_ * H_ * 2, 0);

    conv_enc<<<(int)((size_t)B_ * T_ * E_ / 256), 256>>>(enc);
    conv_all<<<dim3(24576, 1, 8), 256>>>(ws_hh, wa_hh, wo_hh, ws_ih, wa_ih, wo_ih);

    // state-independent gi precompute: 24 ntiles x 64 mtiles x 3 matrices
    pre_gemm_k<<<dim3(24, 64, 3), 256, SMEM_TOTAL>>>();

    // sequential scan
    for (int t = 0; t < T_; t++) {
        step_gemm_k<<<dim3(24, 10), 256, SMEM_TOTAL>>>(dig, t);
        gru_pointwise<<<512, 512>>>(A, dig, t, ws_bih, ws_bhh, wa_bih, wa_bhh,
                                    wo_bih, wo_bhh);
    }
}

// round 8
// speedup vs baseline: 2.7146x; 1.0452x over previous
#include <cuda_runtime.h>
#include <cuda_fp16.h>
#include <cstdint>
#include <math.h>

#define B_ 128
#define T_ 64
#define E_ 2048
#define H_ 1024
#define R_ 8
#define H3 3072

// ==================== helpers (baseline PTX only) ====================
__device__ __forceinline__ uint32_t smem_to_u32(const void* p) {
    uint32_t a;
    asm("{ .reg .u64 t; cvta.to.shared.u64 t, %1; cvt.u32.u64 %0, t; }"
        : "=r"(a) : "l"(p));
    return a;
}
__device__ __forceinline__ uint32_t swz(uint32_t b) { return b ^ ((b >> 3) & 0x70); }

__device__ __forceinline__ void cpa16(uint32_t dst, const void* src) {
    asm volatile("cp.async.cg.shared.global [%0], [%1], 16;" :: "r"(dst), "l"(src));
}
__device__ __forceinline__ void ldm_x4(uint32_t* r, uint32_t a) {
    asm volatile("ldmatrix.sync.aligned.m8n8.x4.shared.b16 {%0,%1,%2,%3}, [%4];"
                 : "=r"(r[0]), "=r"(r[1]), "=r"(r[2]), "=r"(r[3]) : "r"(a));
}
__device__ __forceinline__ void mma16816(float* c, const uint32_t* a, const uint32_t* b) {
    asm volatile(
        "mma.sync.aligned.m16n8k16.row.col.f32.f16.f16.f32 "
        "{%0,%1,%2,%3}, {%4,%5,%6,%7}, {%8,%9}, {%0,%1,%2,%3};"
        : "+f"(c[0]), "+f"(c[1]), "+f"(c[2]), "+f"(c[3])
        : "r"(a[0]), "r"(a[1]), "r"(a[2]), "r"(a[3]), "r"(b[0]), "r"(b[1]));
}

// ==================== scratch (static device, allocation-free) ====================
// GI arrays are T-MAJOR: row index = t*B + b
__device__ float d_GI_s[(size_t)B_ * T_ * H3];
__device__ float d_GI_a[(size_t)B_ * T_ * H3];
__device__ float d_GI_o[(size_t)B_ * T_ * H3];
__device__ float d_G[1280 * H3];

__device__ __half d_enc_h[(size_t)B_ * T_ * E_];  // row = b*T + t (input layout)
__device__ __half d_S_h[(size_t)B_ * R_ * H_];

// W images (fp16). Per ntile (128 n-rows) per k64 chunk: a 16KB SW128 tile.
// Element (n,k): nt=n>>7, r=n&127, cc=k>>6, j=k&63:
//   elem = ((nt*KWC + cc) << 13) + swz(r*128 + j*2)/2
__device__ __align__(16) __half d_img_hh_s[3072 * 1024];
__device__ __align__(16) __half d_img_hh_a[3072 * 1024];
__device__ __align__(16) __half d_img_hh_o[3072 * 1024];
__device__ __align__(16) __half d_img_ihE_s[3072 * 2048];
__device__ __align__(16) __half d_img_ihE_a[3072 * 2048];
__device__ __align__(16) __half d_img_ihE_o[3072 * 2048];
__device__ __align__(16) __half d_img_ihH_s[3072 * 1024];
__device__ __align__(16) __half d_img_ihH_a[3072 * 1024];

// ==================== conversion kernels ====================
__global__ void conv_enc(const float* __restrict__ enc) {
    size_t idx = (size_t)blockIdx.x * 256 + threadIdx.x;
    d_enc_h[idx] = __float2half_rn(enc[idx]);
}

__device__ __forceinline__ size_t wimg_off(int n, int k, int kwc) {
    int nt = n >> 7, r = n & 127;
    int cc = k >> 6, j = k & 63;
    uint32_t byte = (uint32_t)((r << 7) + (j << 1));
    return (((size_t)(nt * kwc + cc)) << 13) + (swz(byte) >> 1);
}

__global__ void conv_all(const float* __restrict__ ws_hh, const float* __restrict__ wa_hh,
                         const float* __restrict__ wo_hh, const float* __restrict__ ws_ih,
                         const float* __restrict__ wa_ih, const float* __restrict__ wo_ih) {
    int z = blockIdx.z;
    const float* src;
    __half* img;
    int ld, off, kb;
    switch (z) {
        case 0: src = ws_hh; img = d_img_hh_s;  ld = 1024; off = 0;    kb = 10; break;
        case 1: src = wa_hh; img = d_img_hh_a;  ld = 1024; off = 0;    kb = 10; break;
        case 2: src = wo_hh; img = d_img_hh_o;  ld = 1024; off = 0;    kb = 10; break;
        case 3: src = ws_ih; img = d_img_ihE_s; ld = 3072; off = 0;    kb = 11; break;
        case 4: src = wa_ih; img = d_img_ihE_a; ld = 3072; off = 0;    kb = 11; break;
        case 5: src = wo_ih; img = d_img_ihE_o; ld = 2048; off = 0;    kb = 11; break;
        case 6: src = ws_ih; img = d_img_ihH_s; ld = 3072; off = 2048; kb = 10; break;
        default: src = wa_ih; img = d_img_ihH_a; ld = 3072; off = 2048; kb = 10; break;
    }
    size_t idx = (size_t)blockIdx.x * 256 + threadIdx.x;
    if (idx >= ((size_t)3072 << kb)) return;
    int n = (int)(idx >> kb);
    int k = (int)(idx & ((1 << kb) - 1));
    float x = src[(size_t)n * ld + off + k];
    img[wimg_off(n, k, 1 << (kb - 6))] = __float2half_rn(x);
}

// ==================== GEMM core: 128x128 tile, k64 chunks, 3-stage ====================
static constexpr int STAGE = 32768;                  // A 16K + W 16K
static constexpr int SMEM_TOTAL = 1024 + 3 * STAGE;  // 99328

__device__ __forceinline__ void load_stage(uint32_t st, const __half* __restrict__ Ah,
                                           int astride, const int* __restrict__ rowmap,
                                           int koff, const __half* __restrict__ Wchunk,
                                           int tid) {
#pragma unroll
    for (int i = 0; i < 4; i++) {
        int lin = tid + (i << 8);
        int row = lin >> 3, seg = lin & 7;
        uint32_t so = swz((uint32_t)((row << 7) + (seg << 4)));
        cpa16(st + so, Ah + (size_t)rowmap[row] * astride + koff + (seg << 3));
    }
    const char* ws = (const char*)Wchunk;
#pragma unroll
    for (int i = 0; i < 4; i++) {
        uint32_t o = (uint32_t)((tid + (i << 8)) << 4);
        cpa16(st + 16384 + o, ws + o);
    }
    asm volatile("cp.async.commit_group;" ::: "memory");
}

// C(128x128) = Arows(128 x K) * W(128 x K)^T, single-pass fp16
__device__ void tc_gemm(const __half* __restrict__ Ah, int astride, int kchunks,
                        const __half* __restrict__ Wimg,  // pre-offset to this ntile
                        const int* __restrict__ rowmap, float* __restrict__ Cmn) {
    extern __shared__ char smem[];
    uint32_t sb = smem_to_u32(smem) + 1024;
    const int tid = threadIdx.x;
    const int wid = tid >> 5;
    const int lid = tid & 31;
    const int wm = (wid >> 2) << 6;  // 0 or 64
    const int wn = (wid & 3) << 5;   // 0,32,64,96

    const int a_r = (lid & 7) | (((lid >> 3) & 1) << 3);
    const int a_kb = ((lid >> 4) & 1) << 4;
    const int w_r = (lid & 7) | (((lid >> 4) & 1) << 3);
    const int w_kb = ((lid >> 3) & 1) << 4;

    float acc[4][4][4];
#pragma unroll
    for (int i = 0; i < 4; i++)
#pragma unroll
        for (int j = 0; j < 4; j++)
#pragma unroll
            for (int q = 0; q < 4; q++) acc[i][j][q] = 0.f;

#pragma unroll
    for (int c = 0; c < 2; c++)
        if (c < kchunks)
            load_stage(sb + c * STAGE, Ah, astride, rowmap, c << 6,
                       Wimg + ((size_t)c << 13), tid);

    int stage = 0;
    for (int c = 0; c < kchunks; c++) {
        if (c + 1 < kchunks) asm volatile("cp.async.wait_group 1;" ::: "memory");
        else                 asm volatile("cp.async.wait_group 0;" ::: "memory");
        __syncthreads();
        if (c + 2 < kchunks) {
            int ns = stage + 2;
            if (ns >= 3) ns -= 3;
            load_stage(sb + ns * STAGE, Ah, astride, rowmap, (c + 2) << 6,
                       Wimg + ((size_t)(c + 2) << 13), tid);
        }
        uint32_t stA = sb + stage * STAGE;
        uint32_t stW = stA + 16384;
#pragma unroll
        for (int ks = 0; ks < 4; ks++) {
            uint32_t wf[8];
#pragma unroll
            for (int p = 0; p < 2; p++) {
                uint32_t rowb = (uint32_t)((wn + (p << 4) + w_r) << 7);
                ldm_x4(wf + (p << 2), stW + swz(rowb + (ks << 5) + w_kb));
            }
#pragma unroll
            for (int mt = 0; mt < 4; mt++) {
                uint32_t af[4];
                uint32_t rowb = (uint32_t)((wm + (mt << 4) + a_r) << 7);
                ldm_x4(af, stA + swz(rowb + (ks << 5) + a_kb));
#pragma unroll
                for (int nt = 0; nt < 4; nt++)
                    mma16816(acc[mt][nt], af, wf + (nt << 1));
            }
        }
        if (++stage >= 3) stage = 0;
    }

    // epilogue
    const int mrow = lid >> 2;
    const int ncol = (lid & 3) << 1;
#pragma unroll
    for (int mt = 0; mt < 4; mt++) {
#pragma unroll
        for (int nt = 0; nt < 4; nt++) {
            float* c0 = Cmn + (size_t)(wm + (mt << 4) + mrow) * H3 + wn + (nt << 3) + ncol;
            *(float2*)c0 = make_float2(acc[mt][nt][0], acc[mt][nt][1]);
            *(float2*)(c0 + 8 * H3) = make_float2(acc[mt][nt][2], acc[mt][nt][3]);
        }
    }
}

// ==================== GEMM wrappers ====================
// pre batch: covers timesteps [tbase, tbase + gridDim.y)
// GI row for (t, b) = t*B + b; A row in d_enc_h for (t, b) = b*T + t
__global__ __launch_bounds__(256, 2) void pre_gemm_k(int tbase) {
    __shared__ int rowmap[128];
    int t = tbase + blockIdx.y;
    if (threadIdx.x < 128) rowmap[threadIdx.x] = threadIdx.x * T_ + t;
    __syncthreads();
    const __half* img;
    float* C;
    if (blockIdx.z == 0)      { img = d_img_ihE_s; C = d_GI_s; }
    else if (blockIdx.z == 1) { img = d_img_ihE_a; C = d_GI_a; }
    else                      { img = d_img_ihE_o; C = d_GI_o; }
    int nt = blockIdx.x;
    size_t woff = (size_t)nt * 32 * 8192;  // 32 k64-chunks per 128-col ntile
    tc_gemm(d_enc_h, E_, 32, img + woff, rowmap,
            C + ((size_t)t * B_) * H3 + nt * 128);
}

// virtual row layout in d_G (1280 rows x 3072):
//   [0,128) spk gh | [128,256) adr gh | [256,1024) oth gh |
//   [1024,1152) spk ih-state | [1152,1280) adr ih-state
__global__ __launch_bounds__(256, 2) void step_gemm_k(const int* __restrict__ dig, int t) {
    __shared__ int rowmap[128];
    int my = blockIdx.y;
    int m0 = my << 7;
    if (threadIdx.x < 128) {
        int i = threadIdx.x;
        int m = m0 + i;
        int b, role;
        if (m < 256 || m >= 1024) {
            b = i;
            int which = (my == 0) ? 0 : (my == 1) ? 1 : (my == 8) ? 1 : 0;
            role = dig[((size_t)(b * T_ + t)) * 2 + which];
        } else {
            int idx = m - 256;
            b = idx / 6;
            int k = idx % 6;
            int spk = dig[((size_t)(b * T_ + t)) * 2];
            int adr = dig[((size_t)(b * T_ + t)) * 2 + 1];
            int cnt = 0;
            role = 0;
#pragma unroll
            for (int rr = 0; rr < R_; rr++) {
                if (rr != spk && rr != adr) {
                    if (cnt == k) role = rr;
                    cnt++;
                }
            }
        }
        rowmap[i] = (b << 3) + role;
    }
    __syncthreads();
    const __half* img;
    if (my == 0)      img = d_img_hh_s;
    else if (my == 1) img = d_img_hh_a;
    else if (my < 8)  img = d_img_hh_o;
    else if (my == 8) img = d_img_ihH_s;
    else              img = d_img_ihH_a;
    int nt = blockIdx.x;
    size_t woff = (size_t)nt * 16 * 8192;  // 16 k64-chunks per ntile
    tc_gemm(d_S_h, H_, 16, img + woff, rowmap, d_G + (size_t)m0 * H3 + nt * 128);
}

// ==================== pointwise GRU update (float4) ====================
__global__ __launch_bounds__(512) void gru_pointwise(
    float* __restrict__ A, const int* __restrict__ dig, int t,
    const float* __restrict__ bih_s, const float* __restrict__ bhh_s,
    const float* __restrict__ bih_a, const float* __restrict__ bhh_a,
    const float* __restrict__ bih_o, const float* __restrict__ bhh_o) {
    int i4 = blockIdx.x * 512 + threadIdx.x;  // < B*R*H/4
    int idx = i4 << 2;
    int h = idx & (H_ - 1);
    int br = idx >> 10;
    int r = br & 7, b = br >> 3;
    int spk = dig[((size_t)(b * T_ + t)) * 2];
    int adr = dig[((size_t)(b * T_ + t)) * 2 + 1];
    const float *GI, *gihs = nullptr, *bih, *bhh;
    int ghrow;
    if (r == spk) {
        ghrow = b; gihs = d_G + (size_t)(1024 + b) * H3;
        GI = d_GI_s; bih = bih_s; bhh = bhh_s;
    } else if (r == adr) {
        ghrow = 128 + b; gihs = d_G + (size_t)(1152 + b) * H3;
        GI = d_GI_a; bih = bih_a; bhh = bhh_a;
    } else {
        int k = r - (spk < r ? 1 : 0) - (adr < r ? 1 : 0);
        ghrow = 256 + b * 6 + k;
        GI = d_GI_o; bih = bih_o; bhh = bhh_o;
    }
    // t-major GI: row = t*B + b
    const float* gi = GI + ((size_t)t * B_ + b) * H3 + h;
    const float* gh = d_G + (size_t)ghrow * H3 + h;
    float4 gir = *(const float4*)(gi);
    float4 giz = *(const float4*)(gi + H_);
    float4 gin = *(const float4*)(gi + 2 * H_);
    if (gihs) {
        const float* gs = gihs + h;
        float4 s0 = *(const float4*)(gs);
        float4 s1 = *(const float4*)(gs + H_);
        float4 s2 = *(const float4*)(gs + 2 * H_);
        gir.x += s0.x; gir.y += s0.y; gir.z += s0.z; gir.w += s0.w;
        giz.x += s1.x; giz.y += s1.y; giz.z += s1.z; giz.w += s1.w;
        gin.x += s2.x; gin.y += s2.y; gin.z += s2.z; gin.w += s2.w;
    }
    float4 ghr = *(const float4*)(gh);
    float4 ghz = *(const float4*)(gh + H_);
    float4 ghn = *(const float4*)(gh + 2 * H_);
    float4 b0 = *(const float4*)(bih + h);
    float4 b1 = *(const float4*)(bih + H_ + h);
    float4 b2 = *(const float4*)(bih + 2 * H_ + h);
    float4 c0 = *(const float4*)(bhh + h);
    float4 c1 = *(const float4*)(bhh + H_ + h);
    float4 c2 = *(const float4*)(bhh + 2 * H_ + h);
    float4 hold = *(const float4*)(A + idx);
    float out[4];
    __half outh[4];
#pragma unroll
    for (int q = 0; q < 4; q++) {
        float vr = ((&gir.x)[q] + (&b0.x)[q]) + ((&ghr.x)[q] + (&c0.x)[q]);
        float vz = ((&giz.x)[q] + (&b1.x)[q]) + ((&ghz.x)[q] + (&c1.x)[q]);
        float hn = (&ghn.x)[q] + (&c2.x)[q];
        float rg = 1.f / (1.f + expf(-vr));
        float zg = 1.f / (1.f + expf(-vz));
        float ng = tanhf((&gin.x)[q] + (&b2.x)[q] + rg * hn);
        float nv = (1.f - zg) * ng + zg * (&hold.x)[q];
        out[q] = nv;
        outh[q] = __float2half_rn(nv);
    }
    *(float4*)(A + idx) = make_float4(out[0], out[1], out[2], out[3]);
    *(uint2*)(&d_S_h[idx]) = *(uint2*)outh;
}

static void* sym_addr(const void* sym) {
    void* p = nullptr;
    cudaGetSymbolAddress(&p, sym);
    return p;
}

extern "C" void kernel_launch(void* const* d_in, const int* in_sizes, int n_in,
                              void* d_out, int out_size) {
    (void)in_sizes; (void)n_in; (void)out_size;
    const float* enc    = (const float*)d_in[0];
    const int*   dig    = (const int*)d_in[1];
    const float* ws_ih  = (const float*)d_in[2];
    const float* ws_hh  = (const float*)d_in[3];
    const float* ws_bih = (const float*)d_in[4];
    const float* ws_bhh = (const float*)d_in[5];
    const float* wa_ih  = (const float*)d_in[6];
    const float* wa_hh  = (const float*)d_in[7];
    const float* wa_bih = (const float*)d_in[8];
    const float* wa_bhh = (const float*)d_in[9];
    const float* wo_ih  = (const float*)d_in[10];
    const float* wo_hh  = (const float*)d_in[11];
    const float* wo_bih = (const float*)d_in[12];
    const float* wo_bhh = (const float*)d_in[13];
    float* A = (float*)d_out;

    // one-time resources (created on the non-captured correctness call)
    static bool init = false;
    static cudaStream_t s2;
    static cudaEvent_t evFork, evPre[16];
    if (!init) {
        cudaStreamCreateWithFlags(&s2, cudaStreamNonBlocking);
        cudaEventCreateWithFlags(&evFork, cudaEventDisableTiming);
        for (int i = 0; i < 16; i++)
            cudaEventCreateWithFlags(&evPre[i], cudaEventDisableTiming);
        cudaFuncSetAttribute(pre_gemm_k, cudaFuncAttributeMaxDynamicSharedMemorySize,
                             SMEM_TOTAL);
        cudaFuncSetAttribute(step_gemm_k, cudaFuncAttributeMaxDynamicSharedMemorySize,
                             SMEM_TOTAL);
        init = true;
    }

    cudaMemsetAsync(d_out, 0, (size_t)B_ * R_ * H_ * sizeof(float), 0);
    cudaMemsetAsync(sym_addr(d_S_h), 0, (size_t)B_ * R_ * H_ * 2, 0);

    conv_enc<<<(int)((size_t)B_ * T_ * E_ / 256), 256>>>(enc);
    conv_all<<<dim3(24576, 1, 8), 256>>>(ws_hh, wa_hh, wo_hh, ws_ih, wa_ih, wo_ih);

    // fork: precompute batches on s2 (4 timesteps per batch, 288 CTAs each)
    cudaEventRecord(evFork, 0);
    cudaStreamWaitEvent(s2, evFork, 0);
    for (int i = 0; i < 16; i++) {
        pre_gemm_k<<<dim3(24, 4, 3), 256, SMEM_TOTAL, s2>>>(i * 4);
        cudaEventRecord(evPre[i], s2);
    }

    // sequential scan on default stream; pointwise(t) joins pre batch t/4
    for (int t = 0; t < T_; t++) {
        step_gemm_k<<<dim3(24, 10), 256, SMEM_TOTAL>>>(dig, t);
        if ((t & 3) == 0) cudaStreamWaitEvent(0, evPre[t >> 2], 0);
        gru_pointwise<<<512, 512>>>(A, dig, t, ws_bih, ws_bhh, wa_bih, wa_bhh,
                                    wo_bih, wo_bhh);
    }
}